// round 14
// baseline (speedup 1.0000x reference)
#include <cuda_runtime.h>
#include <cuda_bf16.h>
#include <cuda_fp16.h>
#include <cstdint>

// Problem constants
#define NB   64      // batch
#define TT   512     // time steps
#define DD   512     // input dim
#define HH   512     // hidden dim
#define G3   1536    // 3*H

// Scratch (device globals: allocation-free)
__device__ float    g_xm[(size_t)2 * NB * TT * G3];   // [dir][n][t][3H]
// fp16 h (single precision pass), fragment-ready:
//   [dir][par][row(64)][kt(32)][tq(4)][2]  cell = { h(k2), h(k2+4) } fp16x2
__device__ unsigned g_hbf[2 * 2 * 64 * 256];
__device__ unsigned g_arrive[2];                      // monotonic barrier counters

// ---- fp16 packing helpers ----
__device__ __forceinline__ unsigned packh(float odd_k, float even_k) {
    unsigned r;
    asm("cvt.rn.f16x2.f32 %0, %1, %2;" : "=r"(r) : "f"(odd_k), "f"(even_k));
    return r;
}
__device__ __forceinline__ float hres(float x) {
    return x - __half2float(__float2half_rn(x));
}
__device__ __forceinline__ void mma_f16(float* c, const unsigned* a,
                                        unsigned b0, unsigned b1) {
    asm volatile(
        "mma.sync.aligned.m16n8k16.row.col.f32.f16.f16.f32 "
        "{%0,%1,%2,%3}, {%4,%5,%6,%7}, {%8,%9}, {%0,%1,%2,%3};"
        : "+f"(c[0]), "+f"(c[1]), "+f"(c[2]), "+f"(c[3])
        : "r"(a[0]), "r"(a[1]), "r"(a[2]), "r"(a[3]), "r"(b0), "r"(b1));
}
__device__ __forceinline__ void ldsm_x4(unsigned& r0, unsigned& r1,
                                        unsigned& r2, unsigned& r3, unsigned sa) {
    asm volatile("ldmatrix.sync.aligned.m8n8.x4.shared.b16 {%0,%1,%2,%3}, [%4];"
                 : "=r"(r0), "=r"(r1), "=r"(r2), "=r"(r3) : "r"(sa));
}
__device__ __forceinline__ unsigned sm32(const void* p) {
    return (unsigned)__cvta_generic_to_shared(p);
}

// -----------------------------------------------------------------------------
// Init: zero fp16 h buffers + barrier counters (65536 uints = 16384 uint4)
// -----------------------------------------------------------------------------
__global__ void init_kernel(unsigned* hbf) {
    int i = blockIdx.x * blockDim.x + threadIdx.x;   // 64*256 = 16384
    reinterpret_cast<uint4*>(hbf)[i] = make_uint4(0u, 0u, 0u, 0u);
    if (i == 0) { g_arrive[0] = 0; g_arrive[1] = 0; }
}

// -----------------------------------------------------------------------------
// Input projection GEMM: fp16 MMA, 2-pass A-side hi/lo split, ldmatrix loads.
// (identical to R12/R13 — proven; accuracy-critical, stays 2-pass)
// -----------------------------------------------------------------------------
#define ARS 12

__global__ __launch_bounds__(256, 2) void sgemm_xm_f16_kernel(
    const float* __restrict__ x,
    const float* __restrict__ Wx_f, const float* __restrict__ Wx_b,
    const float* __restrict__ b_f,  const float* __restrict__ b_b,
    float* __restrict__ xm)
{
    const int dir = blockIdx.z;
    const float* __restrict__ Wx   = dir ? Wx_b : Wx_f;
    const float* __restrict__ bias = dir ? b_b  : b_f;
    float* __restrict__ C = xm + (size_t)dir * (NB * TT) * G3;

    __shared__ __align__(16) unsigned AH[128 * ARS];
    __shared__ __align__(16) unsigned AL[128 * ARS];
    __shared__ __align__(16) unsigned BH[128 * ARS];

    const int t = threadIdx.x;
    const int w = t >> 5;
    const int l = t & 31;
    const int warp_m = w >> 1;
    const int warp_n = w & 1;
    const int gid = l >> 2;
    const int tig = l & 3;

    const int mBase = blockIdx.y * 128;
    const int jBase = blockIdx.x * 128;

    const int aM  = t & 127;
    const int aKg = (t >> 7) * 8;
    const int am  = mBase + aM;
    const int an  = am >> 9;
    const int at0 = am & 511;
    const int ats = dir ? (TT - 1 - at0) : at0;
    const float* __restrict__ aPtr = x + ((size_t)an * TT + ats) * DD + aKg;
    const int aCol = aKg >> 1;

    const int bKp = t & 7;
    const int bN  = (t >> 3) * 4;
    const float* __restrict__ bPtr = Wx + (size_t)(2 * bKp) * G3 + jBase + bN;

    unsigned aAdH[2], aAdL[2], bAdH[4];
    {
        const int rowA = warp_m * 32 + (l & 7) + 8 * ((l >> 3) & 1);
        const int chA  = l >> 4;
#pragma unroll
        for (int mt = 0; mt < 2; mt++) {
            const int r = rowA + mt * 16;
            aAdH[mt] = sm32(&AH[r * ARS + chA * 4]);
            aAdL[mt] = sm32(&AL[r * ARS + chA * 4]);
        }
        const int rowB = warp_n * 64 + (l & 7) + 8 * ((l >> 4) & 1);
        const int chB  = (l >> 3) & 1;
#pragma unroll
        for (int np = 0; np < 4; np++) {
            const int n = rowB + np * 16;
            bAdH[np] = sm32(&BH[n * ARS + chB * 4]);
        }
    }

    float acc[2][8][4];
#pragma unroll
    for (int mt = 0; mt < 2; mt++)
#pragma unroll
        for (int nt = 0; nt < 8; nt++)
#pragma unroll
            for (int r = 0; r < 4; r++) acc[mt][nt][r] = 0.f;

    float4 av0 = *reinterpret_cast<const float4*>(aPtr);
    float4 av1 = *reinterpret_cast<const float4*>(aPtr + 4);
    float4 be  = *reinterpret_cast<const float4*>(bPtr);
    float4 bo  = *reinterpret_cast<const float4*>(bPtr + G3);

    for (int k0 = 0; k0 < DD; k0 += 16) {
        {
            uint4 hh, ll;
            hh.x = packh(av0.y, av0.x); hh.y = packh(av0.w, av0.z);
            hh.z = packh(av1.y, av1.x); hh.w = packh(av1.w, av1.z);
            ll.x = packh(hres(av0.y), hres(av0.x));
            ll.y = packh(hres(av0.w), hres(av0.z));
            ll.z = packh(hres(av1.y), hres(av1.x));
            ll.w = packh(hres(av1.w), hres(av1.z));
            *reinterpret_cast<uint4*>(&AH[aM * ARS + aCol]) = hh;
            *reinterpret_cast<uint4*>(&AL[aM * ARS + aCol]) = ll;
        }
        {
            const float ee[4] = {be.x, be.y, be.z, be.w};
            const float oo[4] = {bo.x, bo.y, bo.z, bo.w};
#pragma unroll
            for (int c = 0; c < 4; c++)
                BH[(bN + c) * ARS + bKp] = packh(oo[c], ee[c]);
        }
        __syncthreads();

        if (k0 + 16 < DD) {
            av0 = *reinterpret_cast<const float4*>(aPtr + k0 + 16);
            av1 = *reinterpret_cast<const float4*>(aPtr + k0 + 20);
            be  = *reinterpret_cast<const float4*>(bPtr + (size_t)(k0 + 16) * G3);
            bo  = *reinterpret_cast<const float4*>(bPtr + (size_t)(k0 + 16) * G3 + G3);
        }

        unsigned ahi[2][4], alo[2][4];
#pragma unroll
        for (int mt = 0; mt < 2; mt++) {
            ldsm_x4(ahi[mt][0], ahi[mt][1], ahi[mt][2], ahi[mt][3], aAdH[mt]);
            ldsm_x4(alo[mt][0], alo[mt][1], alo[mt][2], alo[mt][3], aAdL[mt]);
        }
#pragma unroll
        for (int np = 0; np < 4; np++) {
            unsigned bh[4];
            ldsm_x4(bh[0], bh[1], bh[2], bh[3], bAdH[np]);
#pragma unroll
            for (int tile = 0; tile < 2; tile++) {
                const int nt = np * 2 + tile;
#pragma unroll
                for (int mt = 0; mt < 2; mt++) {
                    mma_f16(acc[mt][nt], ahi[mt], bh[2 * tile], bh[2 * tile + 1]);
                    mma_f16(acc[mt][nt], alo[mt], bh[2 * tile], bh[2 * tile + 1]);
                }
            }
        }
        __syncthreads();
    }

#pragma unroll
    for (int mt = 0; mt < 2; mt++) {
        const int m0 = mBase + warp_m * 32 + mt * 16 + gid;
        const int m1 = m0 + 8;
#pragma unroll
        for (int nt = 0; nt < 8; nt++) {
            const int col = jBase + warp_n * 64 + nt * 8 + tig * 2;
            const float2 bv = *reinterpret_cast<const float2*>(&bias[col]);
            float2 o0, o1;
            o0.x = acc[mt][nt][0] + bv.x;  o0.y = acc[mt][nt][1] + bv.y;
            o1.x = acc[mt][nt][2] + bv.x;  o1.y = acc[mt][nt][3] + bv.y;
            *reinterpret_cast<float2*>(&C[(size_t)m0 * G3 + col]) = o0;
            *reinterpret_cast<float2*>(&C[(size_t)m1 * G3 + col]) = o1;
        }
    }
}

// -----------------------------------------------------------------------------
// Persistent recurrence, occupancy-2, fp16 SINGLE-pass (h in plain fp16).
// Grid dim3(64, 2, 2): x=j-block(8 cols), y=mhalf(32 rows), z=dir.
// 128 threads (4 warps: mt = w&1, khalf = w>>1). Per ki: 2 LDG.64 + 3 MMA.
// -----------------------------------------------------------------------------
#define BFRAG_UINTS  (32 * 3 * 32 * 2)           // 6144 -> 24KB
#define REDF         (6 * 32 * 4)                // 768 floats -> 3KB
#define PMMA_SMEM    ((BFRAG_UINTS + REDF) * 4)  // 27648 B
#define HB_PP        16384                       // uints per (dir,parity)

__global__ __launch_bounds__(128, 2) void gru_persist_mma_kernel(
    const float* __restrict__ Wh_f, const float* __restrict__ Wh_b,
    const float* __restrict__ xm, unsigned* __restrict__ hbf,
    float* __restrict__ out)
{
    extern __shared__ unsigned smu[];
    unsigned* bfr = smu;                         // [kt][gate][lane][2]
    float* red = reinterpret_cast<float*>(smu + BFRAG_UINTS);

    const int dir   = blockIdx.z;
    const int mhalf = blockIdx.y;
    const int j0    = blockIdx.x * 8;
    const float* __restrict__ Wh = dir ? Wh_b : Wh_f;

    const int t  = threadIdx.x;
    const int w  = t >> 5;
    const int l  = t & 31;
    const int g  = l >> 2;
    const int tq = l & 3;
    const int mt    = w & 1;
    const int khalf = w >> 1;

    // ---- fill W B-fragments once (fp16, single pass) ----
    for (int idx = t; idx < 24 * 256; idx += 128) {
        const int c_loc = idx >> 8;
        const int k2    = idx & 255;
        const int gate  = c_loc >> 3;
        const int jj    = c_loc & 7;
        const int col   = gate * HH + j0 + jj;
        const float e = Wh[(size_t)(2 * k2) * G3 + col];
        const float o = Wh[(size_t)(2 * k2 + 1) * G3 + col];
        const int kt = k2 >> 3;
        const int pp = k2 & 7;
        const int rr = pp >> 2;
        const int ts = pp & 3;
        const int off2 = ((kt * 3 + gate) * 32 + jj * 4 + ts) * 2;
        bfr[off2 + rr] = packh(o, e);
    }
    __syncthreads();

    const int row0 = mhalf * 32 + mt * 16 + g;
    const int row1 = row0 + 8;
    const int n0 = row0, n1 = row1;
    const int jA  = j0 + 2 * tq;
    const int k2g = (j0 >> 1) + tq;
    const int wkt   = k2g >> 3;
    const int wpp   = k2g & 7;
    const int wtq   = wpp & 3;
    const int whalf = wpp >> 2;                  // slot within uint2 cell
    const float* xmd = xm + (size_t)dir * (NB * TT) * G3;

    float2 xz0, xr0, xg0, xz1, xr1, xg1;
    float2 hp0 = make_float2(0.f, 0.f), hp1 = make_float2(0.f, 0.f);
    if (khalf == 0) {
        const float* b0 = &xmd[((size_t)n0 * TT + 0) * G3 + jA];
        const float* b1 = &xmd[((size_t)n1 * TT + 0) * G3 + jA];
        xz0 = __ldg((const float2*)(b0));
        xr0 = __ldg((const float2*)(b0 + HH));
        xg0 = __ldg((const float2*)(b0 + 2 * HH));
        xz1 = __ldg((const float2*)(b1));
        xr1 = __ldg((const float2*)(b1 + HH));
        xg1 = __ldg((const float2*)(b1 + 2 * HH));
    }

    const int ktb = khalf * 16;

    for (int s = 0; s < TT; s++) {
        const int p = s & 1;
        const unsigned* __restrict__ hb  = hbf + ((size_t)dir * 2 + p)       * HB_PP;
        unsigned*       __restrict__ hbn = hbf + ((size_t)dir * 2 + (p ^ 1)) * HB_PP;

        float acc[3][4];
#pragma unroll
        for (int nt = 0; nt < 3; nt++)
#pragma unroll
            for (int r = 0; r < 4; r++) acc[nt][r] = 0.f;

        // depth-4 LDG pipeline (uint2 cells)
        uint2 v0[4], v1[4];
#pragma unroll
        for (int pf = 0; pf < 4; pf++) {
            v0[pf] = __ldg(reinterpret_cast<const uint2*>(
                &hb[row0 * 256 + (ktb + pf) * 8 + tq * 2]));
            v1[pf] = __ldg(reinterpret_cast<const uint2*>(
                &hb[row1 * 256 + (ktb + pf) * 8 + tq * 2]));
        }
#pragma unroll
        for (int ki = 0; ki < 16; ki++) {
            const int kt  = ktb + ki;
            const int cur = ki & 3;
            unsigned aH[4];
            aH[0] = v0[cur].x; aH[1] = v1[cur].x;
            aH[2] = v0[cur].y; aH[3] = v1[cur].y;
            if (ki < 12) {
                v0[cur] = __ldg(reinterpret_cast<const uint2*>(
                    &hb[row0 * 256 + (kt + 4) * 8 + tq * 2]));
                v1[cur] = __ldg(reinterpret_cast<const uint2*>(
                    &hb[row1 * 256 + (kt + 4) * 8 + tq * 2]));
            }
#pragma unroll
            for (int nt = 0; nt < 3; nt++) {
                const uint2 bb = *reinterpret_cast<const uint2*>(
                    &bfr[((kt * 3 + nt) * 32 + l) * 2]);
                mma_f16(acc[nt], aH, bb.x, bb.y);
            }
        }

        // ---- split-K exchange (khalf1 -> red -> khalf0) ----
        if (khalf == 1) {
#pragma unroll
            for (int nt = 0; nt < 3; nt++) {
                float4 v = make_float4(acc[nt][0], acc[nt][1], acc[nt][2], acc[nt][3]);
                *reinterpret_cast<float4*>(&red[((mt * 3 + nt) * 32 + l) * 4]) = v;
            }
        }
        __syncthreads();

        if (khalf == 0) {
#pragma unroll
            for (int nt = 0; nt < 3; nt++) {
                const float4 v = *reinterpret_cast<const float4*>(
                    &red[((mt * 3 + nt) * 32 + l) * 4]);
                acc[nt][0] += v.x; acc[nt][1] += v.y;
                acc[nt][2] += v.z; acc[nt][3] += v.w;
            }
            const float z0a = 1.f / (1.f + __expf(-(xz0.x + acc[0][0])));
            const float z0b = 1.f / (1.f + __expf(-(xz0.y + acc[0][1])));
            const float z1a = 1.f / (1.f + __expf(-(xz1.x + acc[0][2])));
            const float z1b = 1.f / (1.f + __expf(-(xz1.y + acc[0][3])));
            const float r0a = 1.f / (1.f + __expf(-(xr0.x + acc[1][0])));
            const float r0b = 1.f / (1.f + __expf(-(xr0.y + acc[1][1])));
            const float r1a = 1.f / (1.f + __expf(-(xr1.x + acc[1][2])));
            const float r1b = 1.f / (1.f + __expf(-(xr1.y + acc[1][3])));
            const float g0a = tanhf(xg0.x + r0a * acc[2][0]);
            const float g0b = tanhf(xg0.y + r0b * acc[2][1]);
            const float g1a = tanhf(xg1.x + r1a * acc[2][2]);
            const float g1b = tanhf(xg1.y + r1b * acc[2][3]);
            const float h0a = (1.f - z0a) * g0a + z0a * hp0.x;
            const float h0b = (1.f - z0b) * g0b + z0b * hp0.y;
            const float h1a = (1.f - z1a) * g1a + z1a * hp1.x;
            const float h1b = (1.f - z1b) * g1b + z1b * hp1.y;
            hp0 = make_float2(h0a, h0b);
            hp1 = make_float2(h1a, h1b);

            // cross-block dependency stores FIRST (single fp16x2 per row)
            hbn[n0 * 256 + wkt * 8 + wtq * 2 + whalf] = packh(h0b, h0a);
            hbn[n1 * 256 + wkt * 8 + wtq * 2 + whalf] = packh(h1b, h1a);

            const int t_out = dir ? (TT - 1 - s) : s;
            *reinterpret_cast<float2*>(
                &out[((size_t)n0 * TT + t_out) * (2 * HH) + dir * HH + jA]) =
                make_float2(h0a, h0b);
            *reinterpret_cast<float2*>(
                &out[((size_t)n1 * TT + t_out) * (2 * HH) + dir * HH + jA]) =
                make_float2(h1a, h1b);

            if (s + 1 < TT) {
                const float* b0 = &xmd[((size_t)n0 * TT + (s + 1)) * G3 + jA];
                const float* b1 = &xmd[((size_t)n1 * TT + (s + 1)) * G3 + jA];
                xz0 = __ldg((const float2*)(b0));
                xr0 = __ldg((const float2*)(b0 + HH));
                xg0 = __ldg((const float2*)(b0 + 2 * HH));
                xz1 = __ldg((const float2*)(b1));
                xr1 = __ldg((const float2*)(b1 + HH));
                xg1 = __ldg((const float2*)(b1 + 2 * HH));
            }
        }

        // ---- per-direction release/acquire barrier (128 blocks) ----
        __syncthreads();
        if (t == 0) {
            unsigned old;
            asm volatile("atom.add.release.gpu.u32 %0, [%1], 1;"
                         : "=r"(old) : "l"(&g_arrive[dir]) : "memory");
            const unsigned target = 128u * (unsigned)(s + 1);
            unsigned cur;
            do {
                asm volatile("ld.acquire.gpu.u32 %0, [%1];"
                             : "=r"(cur) : "l"(&g_arrive[dir]) : "memory");
            } while (cur < target);
        }
        __syncthreads();
    }
}

// -----------------------------------------------------------------------------
// Launch
// -----------------------------------------------------------------------------
extern "C" void kernel_launch(void* const* d_in, const int* in_sizes, int n_in,
                              void* d_out, int out_size)
{
    (void)in_sizes; (void)n_in; (void)out_size;
    const float* x   = (const float*)d_in[0];
    const float* Wxf = (const float*)d_in[1];
    const float* Whf = (const float*)d_in[2];
    const float* bf  = (const float*)d_in[3];
    const float* Wxb = (const float*)d_in[4];
    const float* Whb = (const float*)d_in[5];
    const float* bb  = (const float*)d_in[6];
    float* out = (float*)d_out;

    float* xm;
    unsigned* hbf;
    cudaGetSymbolAddress((void**)&xm, g_xm);
    cudaGetSymbolAddress((void**)&hbf, g_hbf);

    cudaFuncSetAttribute(gru_persist_mma_kernel,
                         cudaFuncAttributeMaxDynamicSharedMemorySize, PMMA_SMEM);

    // 1) h fp16 buffers = 0, barrier counters = 0
    init_kernel<<<64, 256>>>(hbf);

    // 2) input projections: fp16 MMA 2-pass + ldmatrix (accuracy-critical)
    sgemm_xm_f16_kernel<<<dim3(12, 256, 2), 256>>>(x, Wxf, Wxb, bf, bb, xm);

    // 3) persistent recurrence, occupancy-2, single-pass fp16
    gru_persist_mma_kernel<<<dim3(64, 2, 2), 128, PMMA_SMEM>>>(
        Whf, Whb, xm, hbf, out);
}